// round 10
// baseline (speedup 1.0000x reference)
#include <cuda_runtime.h>
#include <cuda_bf16.h>

#define BATCH 4
#define NPTS  16384
#define MCTR  4096
#define KNB   32
#define R2    0.01f
#define RMARG 0.1005f
#define RM2   (RMARG * RMARG)
#define CH    6
#define NCELL 1000          // 10x10x10 per batch
#define TCELL 4096
#define CAP   128
#define CHK   4             // centers per warp in query
#define NPTOT (BATCH * NPTS)   // 65536
#define NCTOT (BATCH * MCTR)   // 16384

// Scratch (__device__ globals: allocation-guard-safe, zero-initialized)
__device__ float4 g_pts4 [NPTOT];      // orig order (x,y,z,p2)
__device__ float4 g_spts4[NPTOT];      // cell-sorted points (x,y,z,bitcast idx)
__device__ float4 g_sctr [NCTOT];      // cell-sorted centers (x,y,z,bitcast m)
__device__ int    g_cell [NPTOT];
__device__ int    g_rank [NPTOT];
__device__ int    g_ccell[NCTOT];
__device__ int    g_crank[NCTOT];
__device__ int    g_cnt  [TCELL];      // point counts (re-zeroed each pass)
__device__ int    g_ccnt [TCELL];      // center counts (re-zeroed each pass)
__device__ int    g_off  [TCELL + 1];
__device__ int    g_coff [TCELL + 1];
__device__ int    g_idx  [NCTOT * KNB];

__device__ __forceinline__ int cell_of(float x, float y, float z) {
    int ci = min(9, max(0, (int)(x * 10.0f)));
    int cj = min(9, max(0, (int)(y * 10.0f)));
    int ck = min(9, max(0, (int)(z * 10.0f)));
    return (ci * 10 + cj) * 10 + ck;
}

// ---------------------------------------------------------------------------
// pack + count: points AND centers in one launch
// ---------------------------------------------------------------------------
__global__ __launch_bounds__(256) void pack_count_kernel(const float* __restrict__ pts,
                                                         const float* __restrict__ ctr) {
    int t = blockIdx.x * blockDim.x + threadIdx.x;
    if (t < NPTOT) {
        int b = t / NPTS, n = t - b * NPTS;
        const float* p = pts + (size_t)b * 3 * NPTS;
        float x = p[n], y = p[NPTS + n], z = p[2 * NPTS + n];
        float p2 = __fmaf_rn(z, z, __fmaf_rn(y, y, __fmul_rn(x, x)));
        g_pts4[t] = make_float4(x, y, z, p2);
        int gc = b * NCELL + cell_of(x, y, z);
        g_cell[t] = gc;
        g_rank[t] = atomicAdd(&g_cnt[gc], 1);
    } else if (t < NPTOT + NCTOT) {
        int u = t - NPTOT;
        int b = u / MCTR, m = u - b * MCTR;
        const float* c = ctr + (size_t)b * 3 * MCTR;
        float x = c[m], y = c[MCTR + m], z = c[2 * MCTR + m];
        int gc = b * NCELL + cell_of(x, y, z);
        g_ccell[u] = gc;
        g_crank[u] = atomicAdd(&g_ccnt[gc], 1);
    }
}

// ---------------------------------------------------------------------------
// two exclusive scans (points, centers) — single block, warp-shuffle 2-level
// ---------------------------------------------------------------------------
__device__ __forceinline__ void scan4096(const int* __restrict__ cnt,
                                         int* __restrict__ off, int* wsum) {
    int tid  = threadIdx.x;
    int lane = tid & 31, wid = tid >> 5;
    int i0 = tid * 4;
    int v0 = cnt[i0], v1 = cnt[i0 + 1], v2 = cnt[i0 + 2], v3 = cnt[i0 + 3];
    int local = v0 + v1 + v2 + v3;

    int inc = local;
    #pragma unroll
    for (int d = 1; d < 32; d <<= 1) {
        int t = __shfl_up_sync(0xffffffffu, inc, d);
        if (lane >= d) inc += t;
    }
    if (lane == 31) wsum[wid] = inc;
    __syncthreads();
    if (wid == 0) {
        int w = wsum[lane];
        int winc = w;
        #pragma unroll
        for (int d = 1; d < 32; d <<= 1) {
            int t = __shfl_up_sync(0xffffffffu, winc, d);
            if (lane >= d) winc += t;
        }
        wsum[lane] = winc - w;
    }
    __syncthreads();
    int excl = wsum[wid] + inc - local;
    off[i0]     = excl;
    off[i0 + 1] = excl + v0;
    off[i0 + 2] = excl + v0 + v1;
    off[i0 + 3] = excl + v0 + v1 + v2;
    if (tid == 1023) off[TCELL] = excl + local;
}

__global__ __launch_bounds__(1024) void scan_kernel() {
    __shared__ int wsum[32];
    scan4096(g_cnt, g_off, wsum);
    __syncthreads();
    scan4096(g_ccnt, g_coff, wsum);
}

// ---------------------------------------------------------------------------
// atomic-free scatter: points and centers; re-zeroes both count arrays
// ---------------------------------------------------------------------------
__global__ __launch_bounds__(256) void scatter_kernel(const float* __restrict__ ctr) {
    int t = blockIdx.x * blockDim.x + threadIdx.x;
    if (t < TCELL) { g_cnt[t] = 0; g_ccnt[t] = 0; }
    if (t < NPTOT) {
        int n = t % NPTS;
        int pos = g_off[g_cell[t]] + g_rank[t];
        float4 p = g_pts4[t];
        g_spts4[pos] = make_float4(p.x, p.y, p.z, __int_as_float(n));
    } else if (t < NPTOT + NCTOT) {
        int u = t - NPTOT;
        int b = u / MCTR, m = u - b * MCTR;
        const float* c = ctr + (size_t)b * 3 * MCTR;
        float x = c[m], y = c[MCTR + m], z = c[2 * MCTR + m];
        int pos = g_coff[g_ccell[u]] + g_crank[u];
        g_sctr[pos] = make_float4(x, y, z, __int_as_float(m));
    }
}

// ---------------------------------------------------------------------------
// warp selection primitives (ascending, 32 elements across lanes)
// ---------------------------------------------------------------------------
__device__ __forceinline__ int sort32(int v, int lane) {
    #pragma unroll
    for (int k = 2; k <= 32; k <<= 1) {
        #pragma unroll
        for (int j = k >> 1; j > 0; j >>= 1) {
            int part = __shfl_xor_sync(0xffffffffu, v, j);
            bool up = ((lane & k) == 0);
            bool takeMin = (((lane & j) == 0) == up);
            v = takeMin ? min(v, part) : max(v, part);
        }
    }
    return v;
}

__device__ __forceinline__ int merge_lower32(int a, int b, int lane) {
    int brev = __shfl_sync(0xffffffffu, b, 31 - lane);
    int m = min(a, brev);
    #pragma unroll
    for (int j = 16; j > 0; j >>= 1) {
        int part = __shfl_xor_sync(0xffffffffu, m, j);
        bool takeMin = ((lane & j) == 0);
        m = takeMin ? min(m, part) : max(m, part);
    }
    return m;
}

// adaptive top-32 (ascending) of lst[0..eff) padded to ng*32 with INT_MAX
__device__ __forceinline__ int select_top32(int* lst, int eff, int lane) {
    int ng = (eff <= 32) ? 1 : (eff <= 64) ? 2 : (eff <= 96) ? 3 : 4;
    for (int t = eff + lane; t < ng * 32; t += 32) lst[t] = 0x7fffffff;
    __syncwarp();
    int a = sort32(lst[lane], lane);
    if (ng == 1) return a;
    int bb = sort32(lst[32 + lane], lane);
    int m01 = merge_lower32(a, bb, lane);
    if (ng == 2) return m01;
    int cc = sort32(lst[64 + lane], lane);
    if (ng == 3) return merge_lower32(m01, cc, lane);
    int dd = sort32(lst[96 + lane], lane);
    return merge_lower32(m01, merge_lower32(cc, dd, lane), lane);
}

// ---------------------------------------------------------------------------
// chunked query: one warp = 4 cell-sorted centers, shared union-window scan
// ---------------------------------------------------------------------------
__global__ __launch_bounds__(256) void query_kernel() {
    __shared__ int lists[8][CHK][CAP];   // 16 KB
    int gw   = (blockIdx.x * blockDim.x + threadIdx.x) >> 5;   // 0..4095
    int wslt = threadIdx.x >> 5;
    int lane = threadIdx.x & 31;
    int b = gw / (MCTR / CHK);
    int q = gw - b * (MCTR / CHK);

    // fetch this warp's 4 centers (lane h loads, broadcast by shfl)
    float4 sc = make_float4(0.f, 0.f, 0.f, 0.f);
    if (lane < CHK) sc = g_sctr[(size_t)b * MCTR + q * CHK + lane];

    float cx[CHK], cy[CHK], cz[CHK], c2[CHK];
    int   morig[CHK];
    #pragma unroll
    for (int h = 0; h < CHK; h++) {
        cx[h] = __shfl_sync(0xffffffffu, sc.x, h);
        cy[h] = __shfl_sync(0xffffffffu, sc.y, h);
        cz[h] = __shfl_sync(0xffffffffu, sc.z, h);
        morig[h] = __shfl_sync(0xffffffffu, __float_as_int(sc.w), h);
        c2[h] = __fmaf_rn(cz[h], cz[h], __fmaf_rn(cy[h], cy[h], __fmul_rn(cx[h], cx[h])));
    }

    // union window over the 4 centers (per-center windows identical to R9 math)
    int ui0 = 9, ui1 = 0, uj0 = 9, uj1 = 0, uk0 = 9, uk1 = 0;
    float minx = 1e9f, maxx = -1e9f, miny = 1e9f, maxy = -1e9f;
    #pragma unroll
    for (int h = 0; h < CHK; h++) {
        ui0 = min(ui0, max(0, (int)((cx[h] - RMARG) * 10.0f)));
        ui1 = max(ui1, min(9, (int)((cx[h] + RMARG) * 10.0f)));
        uj0 = min(uj0, max(0, (int)((cy[h] - RMARG) * 10.0f)));
        uj1 = max(uj1, min(9, (int)((cy[h] + RMARG) * 10.0f)));
        uk0 = min(uk0, max(0, (int)((cz[h] - RMARG) * 10.0f)));
        uk1 = max(uk1, min(9, (int)((cz[h] + RMARG) * 10.0f)));
        minx = fminf(minx, cx[h]); maxx = fmaxf(maxx, cx[h]);
        miny = fminf(miny, cy[h]); maxy = fmaxf(maxy, cy[h]);
    }

    unsigned below = (1u << lane) - 1u;
    unsigned cnt[CHK];
    #pragma unroll
    for (int h = 0; h < CHK; h++) cnt[h] = 0;

    for (int ci = ui0; ci <= ui1; ci++) {
        float lox = ci * 0.1f, hix = lox + 0.1f;
        float dxm = fmaxf(fmaxf(lox - maxx, minx - hix), 0.0f);   // fat-box dist
        float dx2 = dxm * dxm;
        for (int cj = uj0; cj <= uj1; cj++) {
            float loy = cj * 0.1f, hiy = loy + 0.1f;
            float dym = fmaxf(fmaxf(loy - maxy, miny - hiy), 0.0f);
            if (__fmaf_rn(dym, dym, dx2) >= RM2) continue;   // safe for all 4

            int cb = b * NCELL + (ci * 10 + cj) * 10;
            int start = g_off[cb + uk0];
            int end   = g_off[cb + uk1 + 1];
            for (int pb = start; pb < end; pb += 32) {
                int p = pb + lane;
                bool valid = p < end;
                float4 qv = g_spts4[valid ? p : end - 1];
                float p2 = __fmaf_rn(qv.z, qv.z, __fmaf_rn(qv.y, qv.y, __fmul_rn(qv.x, qv.x)));
                int idxv = __float_as_int(qv.w);
                #pragma unroll
                for (int h = 0; h < CHK; h++) {
                    float cp = __fmaf_rn(cz[h], qv.z, __fmaf_rn(cy[h], qv.y, __fmul_rn(cx[h], qv.x)));
                    float d2 = __fsub_rn(__fadd_rn(c2[h], p2), __fmul_rn(2.0f, cp));
                    bool hit = valid && (d2 < R2);
                    unsigned msk = __ballot_sync(0xffffffffu, hit);
                    unsigned pos = cnt[h] + __popc(msk & below);
                    if (hit && pos < CAP) lists[wslt][h][pos] = idxv;
                    cnt[h] += __popc(msk);
                }
            }
        }
    }

    // per-center selection + output (sequential, warp-collective)
    #pragma unroll
    for (int h = 0; h < CHK; h++) {
        int eff = min((int)cnt[h], CAP);
        int top = select_top32(lists[wslt][h], eff, lane);
        g_idx[((size_t)b * MCTR + morig[h]) * KNB + lane] = (lane < eff) ? top : 0;
    }
}

// ---------------------------------------------------------------------------
// tiled gather: thread owns a 4-m quad for one k, 6 STG.128, coalesced
// ---------------------------------------------------------------------------
__global__ __launch_bounds__(256) void gather_kernel(const float* __restrict__ centers,
                                                     float* __restrict__ out) {
    __shared__ __align__(16) int   idx_s[32][36];   // [k][m]
    __shared__ __align__(16) float cs[3][32];

    int b  = blockIdx.y;
    int m0 = blockIdx.x * 32;
    int tid = threadIdx.x;

    for (int t = tid; t < 32 * 32; t += 256) {
        int ml = t >> 5, k = t & 31;
        idx_s[k][ml] = g_idx[((size_t)(b * MCTR + m0 + ml)) * KNB + k];
    }
    if (tid < 96) {
        int coord = tid / 32, ml = tid - coord * 32;
        cs[coord][ml] = centers[(size_t)b * 3 * MCTR + coord * MCTR + m0 + ml];
    }
    __syncthreads();

    int lane = tid & 31, wid = tid >> 5;
    int k    = (wid << 2) | (lane >> 3);
    int quad = (lane & 7) << 2;

    const float4* __restrict__ pts = g_pts4 + (size_t)b * NPTS;

    int4 ni = *reinterpret_cast<const int4*>(&idx_s[k][quad]);
    float4 p0 = __ldg(&pts[ni.x]);
    float4 p1 = __ldg(&pts[ni.y]);
    float4 p2 = __ldg(&pts[ni.z]);
    float4 p3 = __ldg(&pts[ni.w]);

    float4 cxq = *reinterpret_cast<const float4*>(&cs[0][quad]);
    float4 cyq = *reinterpret_cast<const float4*>(&cs[1][quad]);
    float4 czq = *reinterpret_cast<const float4*>(&cs[2][quad]);

    float* o = out + (size_t)b * (CH * KNB) * MCTR + (size_t)k * MCTR + m0 + quad;
    const size_t CHS = (size_t)KNB * MCTR;

    float4 vx = make_float4(p0.x, p1.x, p2.x, p3.x);
    float4 vy = make_float4(p0.y, p1.y, p2.y, p3.y);
    float4 vz = make_float4(p0.z, p1.z, p2.z, p3.z);
    float4 rx = make_float4(__fsub_rn(p0.x, cxq.x), __fsub_rn(p1.x, cxq.y),
                            __fsub_rn(p2.x, cxq.z), __fsub_rn(p3.x, cxq.w));
    float4 ry = make_float4(__fsub_rn(p0.y, cyq.x), __fsub_rn(p1.y, cyq.y),
                            __fsub_rn(p2.y, cyq.z), __fsub_rn(p3.y, cyq.w));
    float4 rz = make_float4(__fsub_rn(p0.z, czq.x), __fsub_rn(p1.z, czq.y),
                            __fsub_rn(p2.z, czq.z), __fsub_rn(p3.z, czq.w));

    *reinterpret_cast<float4*>(o + 0 * CHS) = vx;
    *reinterpret_cast<float4*>(o + 1 * CHS) = vy;
    *reinterpret_cast<float4*>(o + 2 * CHS) = vz;
    *reinterpret_cast<float4*>(o + 3 * CHS) = rx;
    *reinterpret_cast<float4*>(o + 4 * CHS) = ry;
    *reinterpret_cast<float4*>(o + 5 * CHS) = rz;
}

// ---------------------------------------------------------------------------
extern "C" void kernel_launch(void* const* d_in, const int* in_sizes, int n_in,
                              void* d_out, int out_size) {
    const float* pts = (const float*)d_in[0];
    const float* ctr = (const float*)d_in[1];
    if (n_in >= 2 && in_sizes[0] < in_sizes[1]) {
        const float* t = pts; pts = ctr; ctr = t;
    }
    float* out = (float*)d_out;

    pack_count_kernel<<<(NPTOT + NCTOT) / 256, 256>>>(pts, ctr);
    scan_kernel<<<1, 1024>>>();
    scatter_kernel<<<(NPTOT + NCTOT) / 256, 256>>>(ctr);
    query_kernel<<<(NCTOT / CHK) / 8, 256>>>();
    dim3 ggrid(MCTR / 32, BATCH);
    gather_kernel<<<ggrid, 256>>>(ctr, out);
}

// round 11
// speedup vs baseline: 2.1239x; 2.1239x over previous
#include <cuda_runtime.h>
#include <cuda_bf16.h>

#define BATCH 4
#define NPTS  16384
#define MCTR  4096
#define KNB   32
#define R2    0.01f
#define RMARG 0.1005f
#define RM2   (RMARG * RMARG)
#define CH    6
#define NCELL 1000          // 10x10x10 per batch
#define TCELL 4096
#define CAP   128
#define CHK   4             // max centers per warp-chunk (within one cell)
#define NPTOT (BATCH * NPTS)   // 65536
#define NCTOT (BATCH * MCTR)   // 16384

// Scratch (__device__ globals: allocation-guard-safe, zero-initialized)
__device__ float4 g_pts4 [NPTOT];      // orig order (x,y,z,p2)
__device__ float4 g_spts4[NPTOT];      // cell-sorted points (x,y,z,bitcast idx)
__device__ float4 g_sctr [NCTOT];      // cell-sorted centers (x,y,z,bitcast m)
__device__ int    g_pk   [NPTOT];      // packed cell | rank<<12 (points)
__device__ int    g_cpk  [NCTOT];      // packed cell | rank<<12 (centers)
__device__ int    g_cnt  [TCELL];      // point counts (re-zeroed each pass)
__device__ int    g_ccnt [TCELL];      // center counts (re-zeroed each pass)
__device__ int    g_off  [TCELL + 1];
__device__ int    g_coff [TCELL + 1];
__device__ int    g_idx  [NCTOT * KNB];

__device__ __forceinline__ int cell_of(float x, float y, float z) {
    int ci = min(9, max(0, (int)(x * 10.0f)));
    int cj = min(9, max(0, (int)(y * 10.0f)));
    int ck = min(9, max(0, (int)(z * 10.0f)));
    return (ci * 10 + cj) * 10 + ck;
}

// ---------------------------------------------------------------------------
// pack + count: points AND centers in one launch
// ---------------------------------------------------------------------------
__global__ __launch_bounds__(256) void pack_count_kernel(const float* __restrict__ pts,
                                                         const float* __restrict__ ctr) {
    int t = blockIdx.x * blockDim.x + threadIdx.x;
    if (t < NPTOT) {
        int b = t / NPTS, n = t - b * NPTS;
        const float* p = pts + (size_t)b * 3 * NPTS;
        float x = p[n], y = p[NPTS + n], z = p[2 * NPTS + n];
        float p2 = __fmaf_rn(z, z, __fmaf_rn(y, y, __fmul_rn(x, x)));
        g_pts4[t] = make_float4(x, y, z, p2);
        int gc = b * NCELL + cell_of(x, y, z);
        int rank = atomicAdd(&g_cnt[gc], 1);
        g_pk[t] = gc | (rank << 12);
    } else if (t < NPTOT + NCTOT) {
        int u = t - NPTOT;
        int b = u / MCTR, m = u - b * MCTR;
        const float* c = ctr + (size_t)b * 3 * MCTR;
        float x = c[m], y = c[MCTR + m], z = c[2 * MCTR + m];
        int gc = b * NCELL + cell_of(x, y, z);
        int rank = atomicAdd(&g_ccnt[gc], 1);
        g_cpk[u] = gc | (rank << 12);
    }
}

// ---------------------------------------------------------------------------
// two exclusive scans (points, centers) — single block, warp-shuffle 2-level
// ---------------------------------------------------------------------------
__device__ __forceinline__ void scan4096(const int* __restrict__ cnt,
                                         int* __restrict__ off, int* wsum) {
    int tid  = threadIdx.x;
    int lane = tid & 31, wid = tid >> 5;
    int i0 = tid * 4;
    int v0 = cnt[i0], v1 = cnt[i0 + 1], v2 = cnt[i0 + 2], v3 = cnt[i0 + 3];
    int local = v0 + v1 + v2 + v3;

    int inc = local;
    #pragma unroll
    for (int d = 1; d < 32; d <<= 1) {
        int t = __shfl_up_sync(0xffffffffu, inc, d);
        if (lane >= d) inc += t;
    }
    if (lane == 31) wsum[wid] = inc;
    __syncthreads();
    if (wid == 0) {
        int w = wsum[lane];
        int winc = w;
        #pragma unroll
        for (int d = 1; d < 32; d <<= 1) {
            int t = __shfl_up_sync(0xffffffffu, winc, d);
            if (lane >= d) winc += t;
        }
        wsum[lane] = winc - w;
    }
    __syncthreads();
    int excl = wsum[wid] + inc - local;
    off[i0]     = excl;
    off[i0 + 1] = excl + v0;
    off[i0 + 2] = excl + v0 + v1;
    off[i0 + 3] = excl + v0 + v1 + v2;
    if (tid == 1023) off[TCELL] = excl + local;
}

__global__ __launch_bounds__(1024) void scan_kernel() {
    __shared__ int wsum[32];
    scan4096(g_cnt, g_off, wsum);
    __syncthreads();
    scan4096(g_ccnt, g_coff, wsum);
}

// ---------------------------------------------------------------------------
// atomic-free scatter: points and centers; re-zeroes both count arrays
// ---------------------------------------------------------------------------
__global__ __launch_bounds__(256) void scatter_kernel(const float* __restrict__ ctr) {
    int t = blockIdx.x * blockDim.x + threadIdx.x;
    if (t < TCELL) { g_cnt[t] = 0; g_ccnt[t] = 0; }
    if (t < NPTOT) {
        int n = t % NPTS;
        int pk = g_pk[t];
        int pos = g_off[pk & 4095] + (pk >> 12);
        float4 p = g_pts4[t];
        g_spts4[pos] = make_float4(p.x, p.y, p.z, __int_as_float(n));
    } else if (t < NPTOT + NCTOT) {
        int u = t - NPTOT;
        int b = u / MCTR, m = u - b * MCTR;
        const float* c = ctr + (size_t)b * 3 * MCTR;
        float x = c[m], y = c[MCTR + m], z = c[2 * MCTR + m];
        int pk = g_cpk[u];
        int pos = g_coff[pk & 4095] + (pk >> 12);
        g_sctr[pos] = make_float4(x, y, z, __int_as_float(m));
    }
}

// ---------------------------------------------------------------------------
// warp selection primitives (ascending, 32 elements across lanes)
// ---------------------------------------------------------------------------
__device__ __forceinline__ int sort32(int v, int lane) {
    #pragma unroll
    for (int k = 2; k <= 32; k <<= 1) {
        #pragma unroll
        for (int j = k >> 1; j > 0; j >>= 1) {
            int part = __shfl_xor_sync(0xffffffffu, v, j);
            bool up = ((lane & k) == 0);
            bool takeMin = (((lane & j) == 0) == up);
            v = takeMin ? min(v, part) : max(v, part);
        }
    }
    return v;
}

__device__ __forceinline__ int merge_lower32(int a, int b, int lane) {
    int brev = __shfl_sync(0xffffffffu, b, 31 - lane);
    int m = min(a, brev);
    #pragma unroll
    for (int j = 16; j > 0; j >>= 1) {
        int part = __shfl_xor_sync(0xffffffffu, m, j);
        bool takeMin = ((lane & j) == 0);
        m = takeMin ? min(m, part) : max(m, part);
    }
    return m;
}

__device__ __forceinline__ int select_top32(int* lst, int eff, int lane) {
    int ng = (eff <= 32) ? 1 : (eff <= 64) ? 2 : (eff <= 96) ? 3 : 4;
    for (int t = eff + lane; t < ng * 32; t += 32) lst[t] = 0x7fffffff;
    __syncwarp();
    int a = sort32(lst[lane], lane);
    if (ng == 1) return a;
    int bb = sort32(lst[32 + lane], lane);
    int m01 = merge_lower32(a, bb, lane);
    if (ng == 2) return m01;
    int cc = sort32(lst[64 + lane], lane);
    if (ng == 3) return merge_lower32(m01, cc, lane);
    int dd = sort32(lst[96 + lane], lane);
    return merge_lower32(m01, merge_lower32(cc, dd, lane), lane);
}

// ---------------------------------------------------------------------------
// per-cell chunked query: warp = (cell, slot); handles <=4 centers OF ONE CELL
// union window ~= single-center window (centers co-located in a 0.1 cube)
// ---------------------------------------------------------------------------
__global__ __launch_bounds__(256) void query_kernel() {
    __shared__ int lists[8][CHK][CAP];   // 16 KB
    int gw   = (blockIdx.x * blockDim.x + threadIdx.x) >> 5;   // 0..16383
    int wslt = threadIdx.x >> 5;
    int lane = threadIdx.x & 31;

    int cell = gw >> 2;          // 0..4095
    int slot = gw & 3;
    int cbeg = g_coff[cell];
    int cend = g_coff[cell + 1];
    int base = cbeg + slot * CHK;
    int nc   = min(CHK, cend - base);
    if (nc <= 0) return;
    int b = cell / NCELL;        // valid: cells >= 4*NCELL are empty -> returned

    // fetch this chunk's centers (lane h loads, broadcast by shfl)
    float4 sc = make_float4(0.f, 0.f, 0.f, 0.f);
    if (lane < nc) sc = g_sctr[base + lane];

    float cx[CHK], cy[CHK], cz[CHK], c2[CHK];
    int   morig[CHK];
    #pragma unroll
    for (int h = 0; h < CHK; h++) {
        cx[h] = __shfl_sync(0xffffffffu, sc.x, h);
        cy[h] = __shfl_sync(0xffffffffu, sc.y, h);
        cz[h] = __shfl_sync(0xffffffffu, sc.z, h);
        morig[h] = __shfl_sync(0xffffffffu, __float_as_int(sc.w), h);
        c2[h] = __fmaf_rn(cz[h], cz[h], __fmaf_rn(cy[h], cy[h], __fmul_rn(cx[h], cx[h])));
    }

    // union window over the chunk's centers (same per-center math as R9)
    int ui0 = 9, ui1 = 0, uj0 = 9, uj1 = 0, uk0 = 9, uk1 = 0;
    float minx = 1e9f, maxx = -1e9f, miny = 1e9f, maxy = -1e9f;
    for (int h = 0; h < nc; h++) {
        ui0 = min(ui0, max(0, (int)((cx[h] - RMARG) * 10.0f)));
        ui1 = max(ui1, min(9, (int)((cx[h] + RMARG) * 10.0f)));
        uj0 = min(uj0, max(0, (int)((cy[h] - RMARG) * 10.0f)));
        uj1 = max(uj1, min(9, (int)((cy[h] + RMARG) * 10.0f)));
        uk0 = min(uk0, max(0, (int)((cz[h] - RMARG) * 10.0f)));
        uk1 = max(uk1, min(9, (int)((cz[h] + RMARG) * 10.0f)));
        minx = fminf(minx, cx[h]); maxx = fmaxf(maxx, cx[h]);
        miny = fminf(miny, cy[h]); maxy = fmaxf(maxy, cy[h]);
    }

    unsigned below = (1u << lane) - 1u;
    unsigned cnt[CHK];
    #pragma unroll
    for (int h = 0; h < CHK; h++) cnt[h] = 0;

    for (int ci = ui0; ci <= ui1; ci++) {
        float lox = ci * 0.1f, hix = lox + 0.1f;
        float dxm = fmaxf(fmaxf(lox - maxx, minx - hix), 0.0f);   // fat-box dist
        float dx2 = dxm * dxm;
        for (int cj = uj0; cj <= uj1; cj++) {
            float loy = cj * 0.1f, hiy = loy + 0.1f;
            float dym = fmaxf(fmaxf(loy - maxy, miny - hiy), 0.0f);
            if (__fmaf_rn(dym, dym, dx2) >= RM2) continue;   // safe for all chunk centers

            int cb = b * NCELL + (ci * 10 + cj) * 10;
            int start = g_off[cb + uk0];
            int end   = g_off[cb + uk1 + 1];
            for (int pb = start; pb < end; pb += 32) {
                int p = pb + lane;
                bool valid = p < end;
                float4 qv = g_spts4[valid ? p : end - 1];
                float p2 = __fmaf_rn(qv.z, qv.z, __fmaf_rn(qv.y, qv.y, __fmul_rn(qv.x, qv.x)));
                int idxv = __float_as_int(qv.w);
                #pragma unroll
                for (int h = 0; h < CHK; h++) {
                    if (h >= nc) break;   // nc warp-uniform
                    float cp = __fmaf_rn(cz[h], qv.z, __fmaf_rn(cy[h], qv.y, __fmul_rn(cx[h], qv.x)));
                    float d2 = __fsub_rn(__fadd_rn(c2[h], p2), __fmul_rn(2.0f, cp));
                    bool hit = valid && (d2 < R2);
                    unsigned msk = __ballot_sync(0xffffffffu, hit);
                    unsigned pos = cnt[h] + __popc(msk & below);
                    if (hit && pos < CAP) lists[wslt][h][pos] = idxv;
                    cnt[h] += __popc(msk);
                }
            }
        }
    }

    // per-center selection + output
    #pragma unroll
    for (int h = 0; h < CHK; h++) {
        if (h >= nc) break;
        int eff = min((int)cnt[h], CAP);
        int top = select_top32(lists[wslt][h], eff, lane);
        g_idx[((size_t)b * MCTR + morig[h]) * KNB + lane] = (lane < eff) ? top : 0;
    }
}

// ---------------------------------------------------------------------------
// tiled gather: thread owns a 4-m quad for one k, 6 STG.128, coalesced
// ---------------------------------------------------------------------------
__global__ __launch_bounds__(256) void gather_kernel(const float* __restrict__ centers,
                                                     float* __restrict__ out) {
    __shared__ __align__(16) int   idx_s[32][36];   // [k][m]
    __shared__ __align__(16) float cs[3][32];

    int b  = blockIdx.y;
    int m0 = blockIdx.x * 32;
    int tid = threadIdx.x;

    for (int t = tid; t < 32 * 32; t += 256) {
        int ml = t >> 5, k = t & 31;
        idx_s[k][ml] = g_idx[((size_t)(b * MCTR + m0 + ml)) * KNB + k];
    }
    if (tid < 96) {
        int coord = tid / 32, ml = tid - coord * 32;
        cs[coord][ml] = centers[(size_t)b * 3 * MCTR + coord * MCTR + m0 + ml];
    }
    __syncthreads();

    int lane = tid & 31, wid = tid >> 5;
    int k    = (wid << 2) | (lane >> 3);
    int quad = (lane & 7) << 2;

    const float4* __restrict__ pts = g_pts4 + (size_t)b * NPTS;

    int4 ni = *reinterpret_cast<const int4*>(&idx_s[k][quad]);
    float4 p0 = __ldg(&pts[ni.x]);
    float4 p1 = __ldg(&pts[ni.y]);
    float4 p2 = __ldg(&pts[ni.z]);
    float4 p3 = __ldg(&pts[ni.w]);

    float4 cxq = *reinterpret_cast<const float4*>(&cs[0][quad]);
    float4 cyq = *reinterpret_cast<const float4*>(&cs[1][quad]);
    float4 czq = *reinterpret_cast<const float4*>(&cs[2][quad]);

    float* o = out + (size_t)b * (CH * KNB) * MCTR + (size_t)k * MCTR + m0 + quad;
    const size_t CHS = (size_t)KNB * MCTR;

    float4 vx = make_float4(p0.x, p1.x, p2.x, p3.x);
    float4 vy = make_float4(p0.y, p1.y, p2.y, p3.y);
    float4 vz = make_float4(p0.z, p1.z, p2.z, p3.z);
    float4 rx = make_float4(__fsub_rn(p0.x, cxq.x), __fsub_rn(p1.x, cxq.y),
                            __fsub_rn(p2.x, cxq.z), __fsub_rn(p3.x, cxq.w));
    float4 ry = make_float4(__fsub_rn(p0.y, cyq.x), __fsub_rn(p1.y, cyq.y),
                            __fsub_rn(p2.y, cyq.z), __fsub_rn(p3.y, cyq.w));
    float4 rz = make_float4(__fsub_rn(p0.z, czq.x), __fsub_rn(p1.z, czq.y),
                            __fsub_rn(p2.z, czq.z), __fsub_rn(p3.z, czq.w));

    *reinterpret_cast<float4*>(o + 0 * CHS) = vx;
    *reinterpret_cast<float4*>(o + 1 * CHS) = vy;
    *reinterpret_cast<float4*>(o + 2 * CHS) = vz;
    *reinterpret_cast<float4*>(o + 3 * CHS) = rx;
    *reinterpret_cast<float4*>(o + 4 * CHS) = ry;
    *reinterpret_cast<float4*>(o + 5 * CHS) = rz;
}

// ---------------------------------------------------------------------------
extern "C" void kernel_launch(void* const* d_in, const int* in_sizes, int n_in,
                              void* d_out, int out_size) {
    const float* pts = (const float*)d_in[0];
    const float* ctr = (const float*)d_in[1];
    if (n_in >= 2 && in_sizes[0] < in_sizes[1]) {
        const float* t = pts; pts = ctr; ctr = t;
    }
    float* out = (float*)d_out;

    pack_count_kernel<<<(NPTOT + NCTOT) / 256, 256>>>(pts, ctr);
    scan_kernel<<<1, 1024>>>();
    scatter_kernel<<<(NPTOT + NCTOT) / 256, 256>>>(ctr);
    query_kernel<<<(TCELL * CHK) / 8, 256>>>();   // warp per (cell, slot)
    dim3 ggrid(MCTR / 32, BATCH);
    gather_kernel<<<ggrid, 256>>>(ctr, out);
}

// round 12
// speedup vs baseline: 2.9603x; 1.3938x over previous
#include <cuda_runtime.h>
#include <cuda_bf16.h>

#define BATCH 4
#define NPTS  16384
#define MCTR  4096
#define KNB   32
#define R2    0.01f
#define RMARG 0.1005f
#define RM2   (RMARG * RMARG)
#define CH    6
#define NCELL 1000          // 10x10x10 per batch
#define TCELL 4096
#define CAP   128

// Scratch (__device__ globals: allocation-guard-safe, zero-initialized)
__device__ float4 g_pts4 [BATCH * NPTS];     // orig order (x,y,z,p2)
__device__ float4 g_spts4[BATCH * NPTS];     // cell-sorted (x,y,z,bitcast idx)
__device__ int    g_cell [BATCH * NPTS];
__device__ int    g_rank [BATCH * NPTS];
__device__ int    g_cnt  [TCELL];            // re-zeroed each pass
__device__ int    g_off  [TCELL + 1];
__device__ int    g_idx  [BATCH * MCTR * KNB];

// ---------------------------------------------------------------------------
__global__ __launch_bounds__(256) void pack_count_kernel(const float* __restrict__ pts) {
    int t = blockIdx.x * blockDim.x + threadIdx.x;
    if (t >= BATCH * NPTS) return;
    int b = t / NPTS, n = t - b * NPTS;
    const float* p = pts + (size_t)b * 3 * NPTS;
    float x = p[n], y = p[NPTS + n], z = p[2 * NPTS + n];
    float p2 = __fmaf_rn(z, z, __fmaf_rn(y, y, __fmul_rn(x, x)));
    g_pts4[t] = make_float4(x, y, z, p2);
    int ci = min(9, max(0, (int)(x * 10.0f)));
    int cj = min(9, max(0, (int)(y * 10.0f)));
    int ck = min(9, max(0, (int)(z * 10.0f)));
    int gc = b * NCELL + (ci * 10 + cj) * 10 + ck;
    g_cell[t] = gc;
    g_rank[t] = atomicAdd(&g_cnt[gc], 1);
}

// exclusive scan over 4096 counts — warp-shuffle 2-level, single block
__global__ __launch_bounds__(1024) void scan_kernel() {
    __shared__ int wsum[32];
    int tid  = threadIdx.x;
    int lane = tid & 31, wid = tid >> 5;

    int i0 = tid * 4;
    int v0 = g_cnt[i0], v1 = g_cnt[i0 + 1], v2 = g_cnt[i0 + 2], v3 = g_cnt[i0 + 3];
    int local = v0 + v1 + v2 + v3;

    int inc = local;
    #pragma unroll
    for (int d = 1; d < 32; d <<= 1) {
        int t = __shfl_up_sync(0xffffffffu, inc, d);
        if (lane >= d) inc += t;
    }
    if (lane == 31) wsum[wid] = inc;
    __syncthreads();
    if (wid == 0) {
        int w = wsum[lane];
        int winc = w;
        #pragma unroll
        for (int d = 1; d < 32; d <<= 1) {
            int t = __shfl_up_sync(0xffffffffu, winc, d);
            if (lane >= d) winc += t;
        }
        wsum[lane] = winc - w;
    }
    __syncthreads();

    int excl = wsum[wid] + inc - local;
    g_off[i0]     = excl;
    g_off[i0 + 1] = excl + v0;
    g_off[i0 + 2] = excl + v0 + v1;
    g_off[i0 + 3] = excl + v0 + v1 + v2;
    if (tid == 1023) g_off[TCELL] = excl + local;
}

// atomic-free scatter into cell-sorted dense array (idx in .w); re-zeroes g_cnt
__global__ __launch_bounds__(256) void scatter_kernel() {
    int t = blockIdx.x * blockDim.x + threadIdx.x;
    if (t < TCELL) g_cnt[t] = 0;
    if (t >= BATCH * NPTS) return;
    int n = t % NPTS;
    int pos = g_off[g_cell[t]] + g_rank[t];
    float4 p = g_pts4[t];
    g_spts4[pos] = make_float4(p.x, p.y, p.z, __int_as_float(n));
}

// ---------------------------------------------------------------------------
// warp selection primitives (ascending, 32 elements across lanes)
// ---------------------------------------------------------------------------
__device__ __forceinline__ int sort32(int v, int lane) {
    #pragma unroll
    for (int k = 2; k <= 32; k <<= 1) {
        #pragma unroll
        for (int j = k >> 1; j > 0; j >>= 1) {
            int part = __shfl_xor_sync(0xffffffffu, v, j);
            bool up = ((lane & k) == 0);
            bool takeMin = (((lane & j) == 0) == up);
            v = takeMin ? min(v, part) : max(v, part);
        }
    }
    return v;
}

__device__ __forceinline__ int merge_lower32(int a, int b, int lane) {
    int brev = __shfl_sync(0xffffffffu, b, 31 - lane);
    int m = min(a, brev);
    #pragma unroll
    for (int j = 16; j > 0; j >>= 1) {
        int part = __shfl_xor_sync(0xffffffffu, m, j);
        bool takeMin = ((lane & j) == 0);
        m = takeMin ? min(m, part) : max(m, part);
    }
    return m;
}

// ---------------------------------------------------------------------------
// warp-per-center query: 64-pt iterations, column prune + tight z-span,
// adaptive top-32 select
// ---------------------------------------------------------------------------
__global__ __launch_bounds__(256) void query_kernel(const float* __restrict__ centers) {
    __shared__ int lists[8][CAP];
    int gw   = (blockIdx.x * blockDim.x + threadIdx.x) >> 5;
    int wslt = threadIdx.x >> 5;
    int lane = threadIdx.x & 31;
    int b = gw / MCTR, m = gw - b * MCTR;

    const float* c = centers + (size_t)b * 3 * MCTR;
    float cx = c[m], cy = c[MCTR + m], cz = c[2 * MCTR + m];
    float c2 = __fmaf_rn(cz, cz, __fmaf_rn(cy, cy, __fmul_rn(cx, cx)));

    int i0 = max(0, (int)((cx - RMARG) * 10.0f)), i1 = min(9, (int)((cx + RMARG) * 10.0f));
    int j0 = max(0, (int)((cy - RMARG) * 10.0f)), j1 = min(9, (int)((cy + RMARG) * 10.0f));
    int k0 = max(0, (int)((cz - RMARG) * 10.0f)), k1 = min(9, (int)((cz + RMARG) * 10.0f));

    int* lst = lists[wslt];
    unsigned below = (1u << lane) - 1u;
    unsigned cnt = 0;

    for (int ci = i0; ci <= i1; ci++) {
        float lox = ci * 0.1f, hix = lox + 0.1f;
        float dxm = fmaxf(fmaxf(lox - cx, cx - hix), 0.0f);
        float dx2 = dxm * dxm;
        for (int cj = j0; cj <= j1; cj++) {
            float loy = cj * 0.1f, hiy = loy + 0.1f;
            float dym = fmaxf(fmaxf(loy - cy, cy - hiy), 0.0f);
            float dxy2 = __fmaf_rn(dym, dym, dx2);
            if (dxy2 >= RM2) continue;                       // column prune

            // tight z-span: sphere reaches only rz = sqrt(RM2 - dxy2) in z.
            // Conservative: RMARG margin absorbs sqrt/truncation ulp.
            float rz = __fsqrt_rn(RM2 - dxy2);
            int kk0 = max(k0, (int)(fmaxf(cz - rz, 0.0f) * 10.0f));
            int kk1 = min(k1, (int)(fminf(cz + rz, 0.999f) * 10.0f));

            int cb = b * NCELL + (ci * 10 + cj) * 10;        // z-cells contiguous
            int start = g_off[cb + kk0];
            int end   = g_off[cb + kk1 + 1];
            for (int pb = start; pb < end; pb += 64) {
                int p0 = pb + lane;
                int p1 = pb + 32 + lane;
                bool h0 = false, h1 = false;
                int iv0 = 0, iv1 = 0;
                if (p0 < end) {
                    float4 q = g_spts4[p0];
                    float p2 = __fmaf_rn(q.z, q.z, __fmaf_rn(q.y, q.y, __fmul_rn(q.x, q.x)));
                    float cp = __fmaf_rn(cz, q.z, __fmaf_rn(cy, q.y, __fmul_rn(cx, q.x)));
                    float d2 = __fsub_rn(__fadd_rn(c2, p2), __fmul_rn(2.0f, cp));
                    h0 = d2 < R2;
                    iv0 = __float_as_int(q.w);
                }
                if (p1 < end) {
                    float4 q = g_spts4[p1];
                    float p2 = __fmaf_rn(q.z, q.z, __fmaf_rn(q.y, q.y, __fmul_rn(q.x, q.x)));
                    float cp = __fmaf_rn(cz, q.z, __fmaf_rn(cy, q.y, __fmul_rn(cx, q.x)));
                    float d2 = __fsub_rn(__fadd_rn(c2, p2), __fmul_rn(2.0f, cp));
                    h1 = d2 < R2;
                    iv1 = __float_as_int(q.w);
                }
                unsigned m0 = __ballot_sync(0xffffffffu, h0);
                unsigned m1 = __ballot_sync(0xffffffffu, h1);

                unsigned s0 = cnt + __popc(m0 & below);
                if (h0 && s0 < CAP) lst[s0] = iv0;
                unsigned cmid = cnt + __popc(m0);
                unsigned s1 = cmid + __popc(m1 & below);
                if (h1 && s1 < CAP) lst[s1] = iv1;
                cnt = cmid + __popc(m1);
            }
        }
    }

    int eff = min((int)cnt, CAP);
    int ng  = (eff <= 32) ? 1 : (eff <= 64) ? 2 : (eff <= 96) ? 3 : 4;
    for (int t = eff + lane; t < ng * 32; t += 32) lst[t] = 0x7fffffff;
    __syncwarp();

    int top;
    {
        int a = sort32(lst[lane], lane);
        if (ng == 1) {
            top = a;
        } else {
            int bb = sort32(lst[32 + lane], lane);
            int m01 = merge_lower32(a, bb, lane);
            if (ng == 2) {
                top = m01;
            } else {
                int cc = sort32(lst[64 + lane], lane);
                if (ng == 3) {
                    top = merge_lower32(m01, cc, lane);
                } else {
                    int dd = sort32(lst[96 + lane], lane);
                    top = merge_lower32(m01, merge_lower32(cc, dd, lane), lane);
                }
            }
        }
    }

    g_idx[(size_t)gw * KNB + lane] = (lane < eff) ? top : 0;
}

// ---------------------------------------------------------------------------
// tiled gather: thread owns a 4-m quad for one k, 6 STG.128, coalesced
// ---------------------------------------------------------------------------
__global__ __launch_bounds__(256) void gather_kernel(const float* __restrict__ centers,
                                                     float* __restrict__ out) {
    __shared__ __align__(16) int   idx_s[32][36];   // [k][m]
    __shared__ __align__(16) float cs[3][32];

    int b  = blockIdx.y;
    int m0 = blockIdx.x * 32;
    int tid = threadIdx.x;

    for (int t = tid; t < 32 * 32; t += 256) {
        int ml = t >> 5, k = t & 31;
        idx_s[k][ml] = g_idx[((size_t)(b * MCTR + m0 + ml)) * KNB + k];
    }
    if (tid < 96) {
        int coord = tid / 32, ml = tid - coord * 32;
        cs[coord][ml] = centers[(size_t)b * 3 * MCTR + coord * MCTR + m0 + ml];
    }
    __syncthreads();

    int lane = tid & 31, wid = tid >> 5;
    int k    = (wid << 2) | (lane >> 3);
    int quad = (lane & 7) << 2;

    const float4* __restrict__ pts = g_pts4 + (size_t)b * NPTS;

    int4 ni = *reinterpret_cast<const int4*>(&idx_s[k][quad]);
    float4 p0 = __ldg(&pts[ni.x]);
    float4 p1 = __ldg(&pts[ni.y]);
    float4 p2 = __ldg(&pts[ni.z]);
    float4 p3 = __ldg(&pts[ni.w]);

    float4 cxq = *reinterpret_cast<const float4*>(&cs[0][quad]);
    float4 cyq = *reinterpret_cast<const float4*>(&cs[1][quad]);
    float4 czq = *reinterpret_cast<const float4*>(&cs[2][quad]);

    float* o = out + (size_t)b * (CH * KNB) * MCTR + (size_t)k * MCTR + m0 + quad;
    const size_t CHS = (size_t)KNB * MCTR;

    float4 vx = make_float4(p0.x, p1.x, p2.x, p3.x);
    float4 vy = make_float4(p0.y, p1.y, p2.y, p3.y);
    float4 vz = make_float4(p0.z, p1.z, p2.z, p3.z);
    float4 rx = make_float4(__fsub_rn(p0.x, cxq.x), __fsub_rn(p1.x, cxq.y),
                            __fsub_rn(p2.x, cxq.z), __fsub_rn(p3.x, cxq.w));
    float4 ry = make_float4(__fsub_rn(p0.y, cyq.x), __fsub_rn(p1.y, cyq.y),
                            __fsub_rn(p2.y, cyq.z), __fsub_rn(p3.y, cyq.w));
    float4 rz = make_float4(__fsub_rn(p0.z, czq.x), __fsub_rn(p1.z, czq.y),
                            __fsub_rn(p2.z, czq.z), __fsub_rn(p3.z, czq.w));

    *reinterpret_cast<float4*>(o + 0 * CHS) = vx;
    *reinterpret_cast<float4*>(o + 1 * CHS) = vy;
    *reinterpret_cast<float4*>(o + 2 * CHS) = vz;
    *reinterpret_cast<float4*>(o + 3 * CHS) = rx;
    *reinterpret_cast<float4*>(o + 4 * CHS) = ry;
    *reinterpret_cast<float4*>(o + 5 * CHS) = rz;
}

// ---------------------------------------------------------------------------
extern "C" void kernel_launch(void* const* d_in, const int* in_sizes, int n_in,
                              void* d_out, int out_size) {
    const float* pts = (const float*)d_in[0];
    const float* ctr = (const float*)d_in[1];
    if (n_in >= 2 && in_sizes[0] < in_sizes[1]) {
        const float* t = pts; pts = ctr; ctr = t;
    }
    float* out = (float*)d_out;

    pack_count_kernel<<<(BATCH * NPTS) / 256, 256>>>(pts);
    scan_kernel<<<1, 1024>>>();
    scatter_kernel<<<(BATCH * NPTS) / 256, 256>>>();
    query_kernel<<<(BATCH * MCTR) / 8, 256>>>(ctr);
    dim3 ggrid(MCTR / 32, BATCH);
    gather_kernel<<<ggrid, 256>>>(ctr, out);
}

// round 13
// speedup vs baseline: 3.0281x; 1.0229x over previous
#include <cuda_runtime.h>
#include <cuda_bf16.h>

#define BATCH 4
#define NPTS  16384
#define MCTR  4096
#define KNB   32
#define R2    0.01f
#define RMARG 0.1005f
#define RM2   (RMARG * RMARG)
#define CH    6
#define NCELL 1000          // 10x10x10 per batch
#define TCELL 4096
#define CAP   128
#define NPTOT (BATCH * NPTS)   // 65536

// Scratch (__device__ globals: allocation-guard-safe, zero-initialized)
__device__ float4 g_pts4 [NPTOT];      // orig order (x,y,z,p2)
__device__ float4 g_spts4[NPTOT];      // cell-sorted (x,y,z,bitcast idx)
__device__ int    g_pk   [NPTOT];      // packed cell | rank<<12
__device__ int    g_cnt  [TCELL];      // re-zeroed each pass (by scatter)
__device__ int    g_off  [TCELL + 1];
__device__ int    g_idx  [BATCH * MCTR * KNB];
__device__ int    g_ticket;            // reset by scanning block each pass

// ---------------------------------------------------------------------------
// pack + count + (last block) scan
// ---------------------------------------------------------------------------
__global__ __launch_bounds__(256) void pack_count_kernel(const float* __restrict__ pts) {
    int t = blockIdx.x * blockDim.x + threadIdx.x;
    {
        int b = t / NPTS, n = t - b * NPTS;
        const float* p = pts + (size_t)b * 3 * NPTS;
        float x = p[n], y = p[NPTS + n], z = p[2 * NPTS + n];
        float p2 = __fmaf_rn(z, z, __fmaf_rn(y, y, __fmul_rn(x, x)));
        g_pts4[t] = make_float4(x, y, z, p2);
        int ci = min(9, max(0, (int)(x * 10.0f)));
        int cj = min(9, max(0, (int)(y * 10.0f)));
        int ck = min(9, max(0, (int)(z * 10.0f)));
        int gc = b * NCELL + (ci * 10 + cj) * 10 + ck;
        int rank = atomicAdd(&g_cnt[gc], 1);
        g_pk[t] = gc | (rank << 12);
    }

    // last-block-done: final block performs the exclusive scan
    __threadfence();
    __shared__ int isLast;
    if (threadIdx.x == 0) {
        int v = atomicAdd(&g_ticket, 1);
        isLast = (v == (int)gridDim.x - 1);
    }
    __syncthreads();
    if (!isLast) return;

    // scan 4096 counts with this block's 256 threads (16 elems each)
    __shared__ int wsums[8];
    int tid  = threadIdx.x;
    int lane = tid & 31, wid = tid >> 5;
    int base = tid * 16;
    int vals[16];
    int tot = 0;
    #pragma unroll
    for (int i = 0; i < 16; i++) { vals[i] = g_cnt[base + i]; tot += vals[i]; }

    int inc = tot;
    #pragma unroll
    for (int d = 1; d < 32; d <<= 1) {
        int u = __shfl_up_sync(0xffffffffu, inc, d);
        if (lane >= d) inc += u;
    }
    if (lane == 31) wsums[wid] = inc;
    __syncthreads();
    if (tid == 0) {
        int run = 0;
        #pragma unroll
        for (int i = 0; i < 8; i++) { int v = wsums[i]; wsums[i] = run; run += v; }
    }
    __syncthreads();

    int run = wsums[wid] + inc - tot;   // exclusive prefix for this thread's range
    #pragma unroll
    for (int i = 0; i < 16; i++) { g_off[base + i] = run; run += vals[i]; }
    if (tid == 255) g_off[TCELL] = run;
    if (tid == 0)   g_ticket = 0;       // reset for next graph replay
}

// ---------------------------------------------------------------------------
// atomic-free scatter, 2 points/thread (MLP=2); re-zeroes g_cnt
// ---------------------------------------------------------------------------
__global__ __launch_bounds__(256) void scatter_kernel() {
    int t = blockIdx.x * blockDim.x + threadIdx.x;   // 0..32767
    if (t < TCELL) g_cnt[t] = 0;

    int t0 = t, t1 = t + NPTOT / 2;
    int pk0 = g_pk[t0];
    int pk1 = g_pk[t1];
    float4 p0 = g_pts4[t0];
    float4 p1 = g_pts4[t1];
    int off0 = g_off[pk0 & 4095];
    int off1 = g_off[pk1 & 4095];
    int n0 = t0 % NPTS, n1 = t1 % NPTS;
    g_spts4[off0 + (pk0 >> 12)] = make_float4(p0.x, p0.y, p0.z, __int_as_float(n0));
    g_spts4[off1 + (pk1 >> 12)] = make_float4(p1.x, p1.y, p1.z, __int_as_float(n1));
}

// ---------------------------------------------------------------------------
// warp selection primitives (ascending, 32 elements across lanes)
// ---------------------------------------------------------------------------
__device__ __forceinline__ int sort32(int v, int lane) {
    #pragma unroll
    for (int k = 2; k <= 32; k <<= 1) {
        #pragma unroll
        for (int j = k >> 1; j > 0; j >>= 1) {
            int part = __shfl_xor_sync(0xffffffffu, v, j);
            bool up = ((lane & k) == 0);
            bool takeMin = (((lane & j) == 0) == up);
            v = takeMin ? min(v, part) : max(v, part);
        }
    }
    return v;
}

__device__ __forceinline__ int merge_lower32(int a, int b, int lane) {
    int brev = __shfl_sync(0xffffffffu, b, 31 - lane);
    int m = min(a, brev);
    #pragma unroll
    for (int j = 16; j > 0; j >>= 1) {
        int part = __shfl_xor_sync(0xffffffffu, m, j);
        bool takeMin = ((lane & j) == 0);
        m = takeMin ? min(m, part) : max(m, part);
    }
    return m;
}

// ---------------------------------------------------------------------------
// warp-per-center query (R9): 64-pt iterations, column prune, adaptive top-32
// ---------------------------------------------------------------------------
__global__ __launch_bounds__(256) void query_kernel(const float* __restrict__ centers) {
    __shared__ int lists[8][CAP];
    int gw   = (blockIdx.x * blockDim.x + threadIdx.x) >> 5;
    int wslt = threadIdx.x >> 5;
    int lane = threadIdx.x & 31;
    int b = gw / MCTR, m = gw - b * MCTR;

    const float* c = centers + (size_t)b * 3 * MCTR;
    float cx = c[m], cy = c[MCTR + m], cz = c[2 * MCTR + m];
    float c2 = __fmaf_rn(cz, cz, __fmaf_rn(cy, cy, __fmul_rn(cx, cx)));

    int i0 = max(0, (int)((cx - RMARG) * 10.0f)), i1 = min(9, (int)((cx + RMARG) * 10.0f));
    int j0 = max(0, (int)((cy - RMARG) * 10.0f)), j1 = min(9, (int)((cy + RMARG) * 10.0f));
    int k0 = max(0, (int)((cz - RMARG) * 10.0f)), k1 = min(9, (int)((cz + RMARG) * 10.0f));

    int* lst = lists[wslt];
    unsigned below = (1u << lane) - 1u;
    unsigned cnt = 0;

    for (int ci = i0; ci <= i1; ci++) {
        float lox = ci * 0.1f, hix = lox + 0.1f;
        float dxm = fmaxf(fmaxf(lox - cx, cx - hix), 0.0f);
        float dx2 = dxm * dxm;
        for (int cj = j0; cj <= j1; cj++) {
            float loy = cj * 0.1f, hiy = loy + 0.1f;
            float dym = fmaxf(fmaxf(loy - cy, cy - hiy), 0.0f);
            if (__fmaf_rn(dym, dym, dx2) >= RM2) continue;   // column prune

            int cb = b * NCELL + (ci * 10 + cj) * 10;        // z-cells contiguous
            int start = g_off[cb + k0];
            int end   = g_off[cb + k1 + 1];
            for (int pb = start; pb < end; pb += 64) {
                int p0 = pb + lane;
                int p1 = pb + 32 + lane;
                bool h0 = false, h1 = false;
                int iv0 = 0, iv1 = 0;
                if (p0 < end) {
                    float4 q = g_spts4[p0];
                    float p2 = __fmaf_rn(q.z, q.z, __fmaf_rn(q.y, q.y, __fmul_rn(q.x, q.x)));
                    float cp = __fmaf_rn(cz, q.z, __fmaf_rn(cy, q.y, __fmul_rn(cx, q.x)));
                    float d2 = __fsub_rn(__fadd_rn(c2, p2), __fmul_rn(2.0f, cp));
                    h0 = d2 < R2;
                    iv0 = __float_as_int(q.w);
                }
                if (p1 < end) {
                    float4 q = g_spts4[p1];
                    float p2 = __fmaf_rn(q.z, q.z, __fmaf_rn(q.y, q.y, __fmul_rn(q.x, q.x)));
                    float cp = __fmaf_rn(cz, q.z, __fmaf_rn(cy, q.y, __fmul_rn(cx, q.x)));
                    float d2 = __fsub_rn(__fadd_rn(c2, p2), __fmul_rn(2.0f, cp));
                    h1 = d2 < R2;
                    iv1 = __float_as_int(q.w);
                }
                unsigned m0 = __ballot_sync(0xffffffffu, h0);
                unsigned m1 = __ballot_sync(0xffffffffu, h1);

                unsigned s0 = cnt + __popc(m0 & below);
                if (h0 && s0 < CAP) lst[s0] = iv0;
                unsigned cmid = cnt + __popc(m0);
                unsigned s1 = cmid + __popc(m1 & below);
                if (h1 && s1 < CAP) lst[s1] = iv1;
                cnt = cmid + __popc(m1);
            }
        }
    }

    int eff = min((int)cnt, CAP);
    int ng  = (eff <= 32) ? 1 : (eff <= 64) ? 2 : (eff <= 96) ? 3 : 4;
    for (int t = eff + lane; t < ng * 32; t += 32) lst[t] = 0x7fffffff;
    __syncwarp();

    int top;
    {
        int a = sort32(lst[lane], lane);
        if (ng == 1) {
            top = a;
        } else {
            int bb = sort32(lst[32 + lane], lane);
            int m01 = merge_lower32(a, bb, lane);
            if (ng == 2) {
                top = m01;
            } else {
                int cc = sort32(lst[64 + lane], lane);
                if (ng == 3) {
                    top = merge_lower32(m01, cc, lane);
                } else {
                    int dd = sort32(lst[96 + lane], lane);
                    top = merge_lower32(m01, merge_lower32(cc, dd, lane), lane);
                }
            }
        }
    }

    g_idx[(size_t)gw * KNB + lane] = (lane < eff) ? top : 0;
}

// ---------------------------------------------------------------------------
// tiled gather (R9): thread owns a 4-m quad for one k, 6 STG.128, coalesced
// ---------------------------------------------------------------------------
__global__ __launch_bounds__(256) void gather_kernel(const float* __restrict__ centers,
                                                     float* __restrict__ out) {
    __shared__ __align__(16) int   idx_s[32][36];   // [k][m]
    __shared__ __align__(16) float cs[3][32];

    int b  = blockIdx.y;
    int m0 = blockIdx.x * 32;
    int tid = threadIdx.x;

    for (int t = tid; t < 32 * 32; t += 256) {
        int ml = t >> 5, k = t & 31;
        idx_s[k][ml] = g_idx[((size_t)(b * MCTR + m0 + ml)) * KNB + k];
    }
    if (tid < 96) {
        int coord = tid / 32, ml = tid - coord * 32;
        cs[coord][ml] = centers[(size_t)b * 3 * MCTR + coord * MCTR + m0 + ml];
    }
    __syncthreads();

    int lane = tid & 31, wid = tid >> 5;
    int k    = (wid << 2) | (lane >> 3);
    int quad = (lane & 7) << 2;

    const float4* __restrict__ pts = g_pts4 + (size_t)b * NPTS;

    int4 ni = *reinterpret_cast<const int4*>(&idx_s[k][quad]);
    float4 p0 = __ldg(&pts[ni.x]);
    float4 p1 = __ldg(&pts[ni.y]);
    float4 p2 = __ldg(&pts[ni.z]);
    float4 p3 = __ldg(&pts[ni.w]);

    float4 cxq = *reinterpret_cast<const float4*>(&cs[0][quad]);
    float4 cyq = *reinterpret_cast<const float4*>(&cs[1][quad]);
    float4 czq = *reinterpret_cast<const float4*>(&cs[2][quad]);

    float* o = out + (size_t)b * (CH * KNB) * MCTR + (size_t)k * MCTR + m0 + quad;
    const size_t CHS = (size_t)KNB * MCTR;

    float4 vx = make_float4(p0.x, p1.x, p2.x, p3.x);
    float4 vy = make_float4(p0.y, p1.y, p2.y, p3.y);
    float4 vz = make_float4(p0.z, p1.z, p2.z, p3.z);
    float4 rx = make_float4(__fsub_rn(p0.x, cxq.x), __fsub_rn(p1.x, cxq.y),
                            __fsub_rn(p2.x, cxq.z), __fsub_rn(p3.x, cxq.w));
    float4 ry = make_float4(__fsub_rn(p0.y, cyq.x), __fsub_rn(p1.y, cyq.y),
                            __fsub_rn(p2.y, cyq.z), __fsub_rn(p3.y, cyq.w));
    float4 rz = make_float4(__fsub_rn(p0.z, czq.x), __fsub_rn(p1.z, czq.y),
                            __fsub_rn(p2.z, czq.z), __fsub_rn(p3.z, czq.w));

    *reinterpret_cast<float4*>(o + 0 * CHS) = vx;
    *reinterpret_cast<float4*>(o + 1 * CHS) = vy;
    *reinterpret_cast<float4*>(o + 2 * CHS) = vz;
    *reinterpret_cast<float4*>(o + 3 * CHS) = rx;
    *reinterpret_cast<float4*>(o + 4 * CHS) = ry;
    *reinterpret_cast<float4*>(o + 5 * CHS) = rz;
}

// ---------------------------------------------------------------------------
extern "C" void kernel_launch(void* const* d_in, const int* in_sizes, int n_in,
                              void* d_out, int out_size) {
    const float* pts = (const float*)d_in[0];
    const float* ctr = (const float*)d_in[1];
    if (n_in >= 2 && in_sizes[0] < in_sizes[1]) {
        const float* t = pts; pts = ctr; ctr = t;
    }
    float* out = (float*)d_out;

    pack_count_kernel<<<NPTOT / 256, 256>>>(pts);
    scatter_kernel<<<(NPTOT / 2) / 256, 256>>>();
    query_kernel<<<(BATCH * MCTR) / 8, 256>>>(ctr);
    dim3 ggrid(MCTR / 32, BATCH);
    gather_kernel<<<ggrid, 256>>>(ctr, out);
}

// round 14
// speedup vs baseline: 3.3888x; 1.1191x over previous
#include <cuda_runtime.h>
#include <cuda_bf16.h>

#define BATCH 4
#define NPTS  16384
#define MCTR  4096
#define KNB   32
#define R2    0.01f
#define RMARG 0.1005f
#define RM2   (RMARG * RMARG)
#define CH    6
#define NCELL 1000          // 10x10x10 per batch
#define TCELL 4096
#define CAP   128

// Scratch (__device__ globals: allocation-guard-safe, zero-initialized)
__device__ float4 g_pts4 [BATCH * NPTS];     // orig order (x,y,z,p2)
__device__ float4 g_spts4[BATCH * NPTS];     // cell-sorted (x,y,z,bitcast idx)
__device__ int    g_cell [BATCH * NPTS];
__device__ int    g_rank [BATCH * NPTS];
__device__ int    g_cnt  [TCELL];            // re-zeroed each pass
__device__ int    g_off  [TCELL + 1];

// ---------------------------------------------------------------------------
__global__ __launch_bounds__(256) void pack_count_kernel(const float* __restrict__ pts) {
    int t = blockIdx.x * blockDim.x + threadIdx.x;
    if (t >= BATCH * NPTS) return;
    int b = t / NPTS, n = t - b * NPTS;
    const float* p = pts + (size_t)b * 3 * NPTS;
    float x = p[n], y = p[NPTS + n], z = p[2 * NPTS + n];
    float p2 = __fmaf_rn(z, z, __fmaf_rn(y, y, __fmul_rn(x, x)));
    g_pts4[t] = make_float4(x, y, z, p2);
    int ci = min(9, max(0, (int)(x * 10.0f)));
    int cj = min(9, max(0, (int)(y * 10.0f)));
    int ck = min(9, max(0, (int)(z * 10.0f)));
    int gc = b * NCELL + (ci * 10 + cj) * 10 + ck;
    g_cell[t] = gc;
    g_rank[t] = atomicAdd(&g_cnt[gc], 1);
}

// exclusive scan over 4096 counts — warp-shuffle 2-level, single block
__global__ __launch_bounds__(1024) void scan_kernel() {
    __shared__ int wsum[32];
    int tid  = threadIdx.x;
    int lane = tid & 31, wid = tid >> 5;

    int i0 = tid * 4;
    int v0 = g_cnt[i0], v1 = g_cnt[i0 + 1], v2 = g_cnt[i0 + 2], v3 = g_cnt[i0 + 3];
    int local = v0 + v1 + v2 + v3;

    int inc = local;
    #pragma unroll
    for (int d = 1; d < 32; d <<= 1) {
        int t = __shfl_up_sync(0xffffffffu, inc, d);
        if (lane >= d) inc += t;
    }
    if (lane == 31) wsum[wid] = inc;
    __syncthreads();
    if (wid == 0) {
        int w = wsum[lane];
        int winc = w;
        #pragma unroll
        for (int d = 1; d < 32; d <<= 1) {
            int t = __shfl_up_sync(0xffffffffu, winc, d);
            if (lane >= d) winc += t;
        }
        wsum[lane] = winc - w;
    }
    __syncthreads();

    int excl = wsum[wid] + inc - local;
    g_off[i0]     = excl;
    g_off[i0 + 1] = excl + v0;
    g_off[i0 + 2] = excl + v0 + v1;
    g_off[i0 + 3] = excl + v0 + v1 + v2;
    if (tid == 1023) g_off[TCELL] = excl + local;
}

// atomic-free scatter into cell-sorted dense array (idx in .w); re-zeroes g_cnt
__global__ __launch_bounds__(256) void scatter_kernel() {
    int t = blockIdx.x * blockDim.x + threadIdx.x;
    if (t < TCELL) g_cnt[t] = 0;
    if (t >= BATCH * NPTS) return;
    int n = t % NPTS;
    int pos = g_off[g_cell[t]] + g_rank[t];
    float4 p = g_pts4[t];
    g_spts4[pos] = make_float4(p.x, p.y, p.z, __int_as_float(n));
}

// ---------------------------------------------------------------------------
// warp selection primitives (ascending, 32 elements across lanes)
// ---------------------------------------------------------------------------
__device__ __forceinline__ int sort32(int v, int lane) {
    #pragma unroll
    for (int k = 2; k <= 32; k <<= 1) {
        #pragma unroll
        for (int j = k >> 1; j > 0; j >>= 1) {
            int part = __shfl_xor_sync(0xffffffffu, v, j);
            bool up = ((lane & k) == 0);
            bool takeMin = (((lane & j) == 0) == up);
            v = takeMin ? min(v, part) : max(v, part);
        }
    }
    return v;
}

__device__ __forceinline__ int merge_lower32(int a, int b, int lane) {
    int brev = __shfl_sync(0xffffffffu, b, 31 - lane);
    int m = min(a, brev);
    #pragma unroll
    for (int j = 16; j > 0; j >>= 1) {
        int part = __shfl_xor_sync(0xffffffffu, m, j);
        bool takeMin = ((lane & j) == 0);
        m = takeMin ? min(m, part) : max(m, part);
    }
    return m;
}

// ---------------------------------------------------------------------------
// warp-per-center query + fused grouping epilogue.
// Block = 8 consecutive centers of one batch. No separate gather kernel.
// ---------------------------------------------------------------------------
__global__ __launch_bounds__(256) void query_kernel(const float* __restrict__ centers,
                                                    float* __restrict__ out) {
    __shared__ int   lists[8][CAP];          // 4 KB
    __shared__ float stage[CH][8][33];       // 6.2 KB: [channel][center][k]

    int gw   = (blockIdx.x * blockDim.x + threadIdx.x) >> 5;
    int wslt = threadIdx.x >> 5;
    int lane = threadIdx.x & 31;
    int b = gw / MCTR, m = gw - b * MCTR;

    const float* c = centers + (size_t)b * 3 * MCTR;
    float cx = c[m], cy = c[MCTR + m], cz = c[2 * MCTR + m];
    float c2 = __fmaf_rn(cz, cz, __fmaf_rn(cy, cy, __fmul_rn(cx, cx)));

    int i0 = max(0, (int)((cx - RMARG) * 10.0f)), i1 = min(9, (int)((cx + RMARG) * 10.0f));
    int j0 = max(0, (int)((cy - RMARG) * 10.0f)), j1 = min(9, (int)((cy + RMARG) * 10.0f));
    int k0 = max(0, (int)((cz - RMARG) * 10.0f)), k1 = min(9, (int)((cz + RMARG) * 10.0f));

    int* lst = lists[wslt];
    unsigned below = (1u << lane) - 1u;
    unsigned cnt = 0;

    for (int ci = i0; ci <= i1; ci++) {
        float lox = ci * 0.1f, hix = lox + 0.1f;
        float dxm = fmaxf(fmaxf(lox - cx, cx - hix), 0.0f);
        float dx2 = dxm * dxm;
        for (int cj = j0; cj <= j1; cj++) {
            float loy = cj * 0.1f, hiy = loy + 0.1f;
            float dym = fmaxf(fmaxf(loy - cy, cy - hiy), 0.0f);
            if (__fmaf_rn(dym, dym, dx2) >= RM2) continue;   // column prune

            int cb = b * NCELL + (ci * 10 + cj) * 10;        // z-cells contiguous
            int start = g_off[cb + k0];
            int end   = g_off[cb + k1 + 1];
            for (int pb = start; pb < end; pb += 64) {
                int p0 = pb + lane;
                int p1 = pb + 32 + lane;
                bool h0 = false, h1 = false;
                int iv0 = 0, iv1 = 0;
                if (p0 < end) {
                    float4 q = g_spts4[p0];
                    float p2 = __fmaf_rn(q.z, q.z, __fmaf_rn(q.y, q.y, __fmul_rn(q.x, q.x)));
                    float cp = __fmaf_rn(cz, q.z, __fmaf_rn(cy, q.y, __fmul_rn(cx, q.x)));
                    float d2 = __fsub_rn(__fadd_rn(c2, p2), __fmul_rn(2.0f, cp));
                    h0 = d2 < R2;
                    iv0 = __float_as_int(q.w);
                }
                if (p1 < end) {
                    float4 q = g_spts4[p1];
                    float p2 = __fmaf_rn(q.z, q.z, __fmaf_rn(q.y, q.y, __fmul_rn(q.x, q.x)));
                    float cp = __fmaf_rn(cz, q.z, __fmaf_rn(cy, q.y, __fmul_rn(cx, q.x)));
                    float d2 = __fsub_rn(__fadd_rn(c2, p2), __fmul_rn(2.0f, cp));
                    h1 = d2 < R2;
                    iv1 = __float_as_int(q.w);
                }
                unsigned m0 = __ballot_sync(0xffffffffu, h0);
                unsigned m1 = __ballot_sync(0xffffffffu, h1);

                unsigned s0 = cnt + __popc(m0 & below);
                if (h0 && s0 < CAP) lst[s0] = iv0;
                unsigned cmid = cnt + __popc(m0);
                unsigned s1 = cmid + __popc(m1 & below);
                if (h1 && s1 < CAP) lst[s1] = iv1;
                cnt = cmid + __popc(m1);
            }
        }
    }

    int eff = min((int)cnt, CAP);
    int ng  = (eff <= 32) ? 1 : (eff <= 64) ? 2 : (eff <= 96) ? 3 : 4;
    for (int t = eff + lane; t < ng * 32; t += 32) lst[t] = 0x7fffffff;
    __syncwarp();

    int top;
    {
        int a = sort32(lst[lane], lane);
        if (ng == 1) {
            top = a;
        } else {
            int bb = sort32(lst[32 + lane], lane);
            int m01 = merge_lower32(a, bb, lane);
            if (ng == 2) {
                top = m01;
            } else {
                int cc = sort32(lst[64 + lane], lane);
                if (ng == 3) {
                    top = merge_lower32(m01, cc, lane);
                } else {
                    int dd = sort32(lst[96 + lane], lane);
                    top = merge_lower32(m01, merge_lower32(cc, dd, lane), lane);
                }
            }
        }
    }

    // ----- fused grouping epilogue -----
    int topidx = (lane < eff) ? top : 0;                 // reference zero-pads
    float4 pq = g_pts4[(size_t)b * NPTS + topidx];       // one gather per lane

    stage[0][wslt][lane] = pq.x;
    stage[1][wslt][lane] = pq.y;
    stage[2][wslt][lane] = pq.z;
    stage[3][wslt][lane] = __fsub_rn(pq.x, cx);
    stage[4][wslt][lane] = __fsub_rn(pq.y, cy);
    stage[5][wslt][lane] = __fsub_rn(pq.z, cz);
    __syncthreads();

    // cooperative write: 192 rows (c*32+k), 8 m-floats each, lane-pair per row
    int tid   = threadIdx.x;
    int mbase = (blockIdx.x * 8) & (MCTR - 1);           // first m in block
    float* ob = out + (size_t)b * (CH * KNB) * MCTR + mbase;

    #pragma unroll
    for (int pass = 0; pass < 2; pass++) {
        int r = (tid >> 1) + pass * 128;                 // output row: c*32 + k
        if (r < CH * KNB) {
            int cch = r >> 5, kk = r & 31;
            int mh = (tid & 1) * 4;                      // half: m 0-3 or 4-7
            float v0 = stage[cch][mh + 0][kk];
            float v1 = stage[cch][mh + 1][kk];
            float v2 = stage[cch][mh + 2][kk];
            float v3 = stage[cch][mh + 3][kk];
            *reinterpret_cast<float4*>(ob + (size_t)r * MCTR + mh) =
                make_float4(v0, v1, v2, v3);
        }
    }
}

// ---------------------------------------------------------------------------
extern "C" void kernel_launch(void* const* d_in, const int* in_sizes, int n_in,
                              void* d_out, int out_size) {
    const float* pts = (const float*)d_in[0];
    const float* ctr = (const float*)d_in[1];
    if (n_in >= 2 && in_sizes[0] < in_sizes[1]) {
        const float* t = pts; pts = ctr; ctr = t;
    }
    float* out = (float*)d_out;

    pack_count_kernel<<<(BATCH * NPTS) / 256, 256>>>(pts);
    scan_kernel<<<1, 1024>>>();
    scatter_kernel<<<(BATCH * NPTS) / 256, 256>>>();
    query_kernel<<<(BATCH * MCTR) / 8, 256>>>(ctr, out);
}